// round 10
// baseline (speedup 1.0000x reference)
#include <cuda_runtime.h>

#define KK    27
#define CH    64
#define CAPK  65536          // per-k entry capacity (expected ~8K)
#define EXT2  0.75f          // KP_EXTENT^2
#define INV_EXT 1.15470053837925f
#define TH2   (1.8675f * 1.8675f)
#define SLICES 22
#define PAD   68             // floats per xs row (272B, 16B-aligned)
#define CNT_STRIDE 64        // 256B between counters -> distinct L2 slices
#define WROWS 16             // rows per warp per tile (8 warps x 16 = 128)

// global scratch (static __device__ — no runtime allocation)
__device__ unsigned g_pack[KK * CAPK];   // q<<16 | ind
__device__ float    g_w[KK * CAPK];
__device__ int      g_cnt[KK * CNT_STRIDE];

// ---------------- packed f32x2 helpers -------------------------------------
#define PACK2(d, lo, hi) \
    asm("mov.b64 %0, {%1, %2};" : "=l"(d) : "r"(__float_as_uint(lo)), "r"(__float_as_uint(hi)))
#define FMA2(acc, a, b) \
    asm("fma.rn.f32x2 %0, %1, %2, %0;" : "+l"(acc) : "l"(a), "l"(b))
#define UNPACK2(lo, hi, v) \
    asm("mov.b64 {%0, %1}, %2;" : "=r"(lo), "=r"(hi) : "l"(v))

__device__ __forceinline__ void red_add_v4(float* p, float a, float b,
                                           float c, float d) {
    asm volatile("red.global.add.v4.f32 [%0], {%1, %2, %3, %4};"
                 :: "l"(p), "f"(a), "f"(b), "f"(c), "f"(d) : "memory");
}

__device__ __forceinline__ void cp8(float* dst_smem, const float* src) {
    unsigned d = (unsigned)__cvta_generic_to_shared(dst_smem);
    asm volatile("cp.async.ca.shared.global [%0], [%1], 8;"
                 :: "r"(d), "l"(src) : "memory");
}
#define CP_COMMIT() asm volatile("cp.async.commit_group;" ::: "memory")
#define CP_WAIT(n)  asm volatile("cp.async.wait_group %0;" :: "n"(n) : "memory")

// ---------------- kernel 0: zero out + counters ----------------------------
__global__ void zero_kernel(float* __restrict__ out, int n4) {
    int i = blockIdx.x * blockDim.x + threadIdx.x;
    if (i < n4) ((float4*)out)[i] = make_float4(0.f, 0.f, 0.f, 0.f);
    if (blockIdx.x == 0 && threadIdx.x < KK)
        g_cnt[threadIdx.x * CNT_STRIDE] = 0;
}

// ---------------- kernel 1: build per-k entry lists (ballot-compacted) -----
__global__ __launch_bounds__(256) void build_kernel(
    const float* __restrict__ q_pts,   // [N,3]
    const float* __restrict__ s_pts,   // [M,3]
    const int*   __restrict__ inds,    // [N,32]
    const float* __restrict__ x,       // [M,64]  (fallback only)
    const float* __restrict__ W,       // [27,64,64] (fallback only)
    const float* __restrict__ kpts,    // [27,3]
    float* __restrict__ out,           // fallback only
    int N, int M)
{
    const int tid  = threadIdx.x;
    const int lane = tid & 31;
    const int p    = blockIdx.x * 256 + tid;
    const int q    = p >> 5;                 // warp-uniform

    float kx = 0.f, ky = 0.f, kz = 0.f;
    if (lane < KK) {
        kx = kpts[lane * 3 + 0];
        ky = kpts[lane * 3 + 1];
        kz = kpts[lane * 3 + 2];
    }

    bool  alive = false;
    float dx = 0.f, dy = 0.f, dz = 0.f;
    int   ind = 0;
    if (p < N * 32) {
        ind = inds[p];
        if ((unsigned)ind < (unsigned)M) {
            float qx = q_pts[q * 3 + 0];
            float qy = q_pts[q * 3 + 1];
            float qz = q_pts[q * 3 + 2];
            dx = s_pts[ind * 3 + 0] - qx;
            dy = s_pts[ind * 3 + 1] - qy;
            dz = s_pts[ind * 3 + 2] - qz;
            alive = (dx * dx + dy * dy + dz * dz) < TH2;   // ~97% reject
        }
    }

    unsigned mask = __ballot_sync(0xFFFFFFFFu, alive);
    while (mask) {
        int src = __ffs(mask) - 1;
        mask &= mask - 1;
        float sdx = __shfl_sync(0xFFFFFFFFu, dx, src);
        float sdy = __shfl_sync(0xFFFFFFFFu, dy, src);
        float sdz = __shfl_sync(0xFFFFFFFFu, dz, src);
        int   sind = __shfl_sync(0xFFFFFFFFu, ind, src);

        float ex = sdx - kx, ey = sdy - ky, ez = sdz - kz;
        float dd = ex * ex + ey * ey + ez * ez;
        if (lane < KK && dd < EXT2) {
            float w = 1.f - sqrtf(dd) * INV_EXT;
            int pos = atomicAdd(&g_cnt[lane * CNT_STRIDE], 1);
            if (pos < CAPK) {
                g_pack[lane * CAPK + pos] =
                    ((unsigned)q << 16) | (unsigned)sind;
                g_w[lane * CAPK + pos] = w;
            } else {
                // correctness fallback (statistically unreachable)
                const float* xr = x + (size_t)sind * CH;
                const float* wk = W + (size_t)lane * CH * CH;
                for (int o = 0; o < CH; o++) {
                    float a = 0.f;
                    for (int c = 0; c < CH; c++) a += xr[c] * wk[c * CH + o];
                    atomicAdd(&out[(size_t)q * CH + o], w * a);
                }
            }
        }
    }
}

// ---------------- kernel 2: warp-decoupled per-k GEMM + scatter ------------
// grid (27, SLICES), 256 threads. Logical tile = 128 rows; warp wid owns rows
// [wid*16, wid*16+16) with a PRIVATE double-buffered smem slice + its own
// cp.async group FIFO. No __syncthreads in the steady-state loop.
// Compute map per warp: rs = lane>>3 (rows rs+{0,4,8,12}), cg = lane&7.
__global__ __launch_bounds__(256, 2) void gemm_kernel(
    const float* __restrict__ W,       // [27,64,64]
    const float* __restrict__ x,       // [M,64]
    float* __restrict__ out)           // [N,64]
{
    extern __shared__ float smem[];
    float* Ws  = smem;                             // 4096 floats
    float* xsW = Ws + CH * CH;                     // 8 * 2 * WROWS * PAD
    int*   qsW = (int*)(xsW + 8 * 2 * WROWS * PAD);   // 8 * 2 * WROWS
    float* swW = (float*)(qsW + 8 * 2 * WROWS);       // 8 * 2 * WROWS

    const int k    = blockIdx.x;
    const int tid  = threadIdx.x;
    const int wid  = tid >> 5;
    const int lane = tid & 31;
    const int rs   = lane >> 3;     // 0..3
    const int cg   = lane & 7;      // 0..7

    const int R = min(g_cnt[k * CNT_STRIDE], CAPK);
    if (R == 0) return;
    const int ntiles = (R + 127) >> 7;
    int t = blockIdx.y;
    if (t >= ntiles) return;

    // per-warp private regions
    float* xw = xsW + wid * (2 * WROWS * PAD);
    int*   qw = qsW + wid * (2 * WROWS);
    float* ww = swW + wid * (2 * WROWS);

    // stage W[k] once (CTA-wide)
    {
        const float4* src = (const float4*)(W + (size_t)k * CH * CH);
        for (int i = tid; i < (CH * CH) / 4; i += 256) ((float4*)Ws)[i] = src[i];
    }

    // warp-local async fetch of its 16 rows of logical tile tt into buffer p
    auto fetch = [&](int tt, int p) {
        int base = (tt << 7) + wid * WROWS;
        float* dstb = xw + p * WROWS * PAD;
        #pragma unroll 4
        for (int i = 0; i < WROWS; i++) {
            int gi = base + i;
            unsigned pk = (gi < R) ? g_pack[k * CAPK + gi] : 0u;  // warp-bcast
            const float* src = x + (size_t)(pk & 0xFFFFu) * CH + 2 * lane;
            cp8(dstb + i * PAD + 2 * lane, src);
        }
        if (lane < WROWS) {
            int gi = base + lane;
            bool v = gi < R;
            unsigned pk = v ? g_pack[k * CAPK + gi] : 0u;
            qw[p * WROWS + lane] = (int)(pk >> 16);
            ww[p * WROWS + lane] = v ? g_w[k * CAPK + gi] : 0.f;
        }
        CP_COMMIT();
    };

    __syncthreads();                 // Ws visible to all warps
    fetch(t, 0);
    int pb = 0;

    for (; t < ntiles; t += SLICES) {
        int nxt = t + SLICES;
        bool hn = nxt < ntiles;
        if (hn) { fetch(nxt, pb ^ 1); CP_WAIT(1); }
        else    { CP_WAIT(0); }
        __syncwarp();                // cp data + qw/ww visible across lanes

        const float* xb = xw + pb * WROWS * PAD;

        unsigned long long acc[4][4];
        #pragma unroll
        for (int a = 0; a < 4; a++)
            #pragma unroll
            for (int b = 0; b < 4; b++) acc[a][b] = 0ull;

        #pragma unroll 4
        for (int cin4 = 0; cin4 < 16; cin4++) {
            float4 xv0 = *(const float4*)&xb[(rs     ) * PAD + 4 * cin4];
            float4 xv1 = *(const float4*)&xb[(rs +  4) * PAD + 4 * cin4];
            float4 xv2 = *(const float4*)&xb[(rs +  8) * PAD + 4 * cin4];
            float4 xv3 = *(const float4*)&xb[(rs + 12) * PAD + 4 * cin4];
            const float* f0 = (const float*)&xv0;
            const float* f1 = (const float*)&xv1;
            const float* f2 = (const float*)&xv2;
            const float* f3 = (const float*)&xv3;
            #pragma unroll
            for (int j = 0; j < 4; j++) {
                int cin = 4 * cin4 + j;
                const ulonglong2* wp =
                    (const ulonglong2*)(Ws + cin * CH + 8 * cg);
                ulonglong2 wv0 = wp[0];
                ulonglong2 wv1 = wp[1];
                unsigned long long px;
                PACK2(px, f0[j], f0[j]);
                FMA2(acc[0][0], px, wv0.x); FMA2(acc[0][1], px, wv0.y);
                FMA2(acc[0][2], px, wv1.x); FMA2(acc[0][3], px, wv1.y);
                PACK2(px, f1[j], f1[j]);
                FMA2(acc[1][0], px, wv0.x); FMA2(acc[1][1], px, wv0.y);
                FMA2(acc[1][2], px, wv1.x); FMA2(acc[1][3], px, wv1.y);
                PACK2(px, f2[j], f2[j]);
                FMA2(acc[2][0], px, wv0.x); FMA2(acc[2][1], px, wv0.y);
                FMA2(acc[2][2], px, wv1.x); FMA2(acc[2][3], px, wv1.y);
                PACK2(px, f3[j], f3[j]);
                FMA2(acc[3][0], px, wv0.x); FMA2(acc[3][1], px, wv0.y);
                FMA2(acc[3][2], px, wv1.x); FMA2(acc[3][3], px, wv1.y);
            }
        }

        // epilogue: scale by wt + v4 reductions (warp-local, gates nobody)
        int base = (t << 7) + wid * WROWS;
        #pragma unroll
        for (int rr = 0; rr < 4; rr++) {
            int row = rs + 4 * rr;
            if (base + row < R) {
                float wt = ww[pb * WROWS + row];
                float* op = out + (size_t)qw[pb * WROWS + row] * CH + 8 * cg;
                unsigned a0, a1, a2, a3, b0, b1, b2, b3;
                UNPACK2(a0, a1, acc[rr][0]);
                UNPACK2(a2, a3, acc[rr][1]);
                UNPACK2(b0, b1, acc[rr][2]);
                UNPACK2(b2, b3, acc[rr][3]);
                red_add_v4(op,
                           wt * __uint_as_float(a0), wt * __uint_as_float(a1),
                           wt * __uint_as_float(a2), wt * __uint_as_float(a3));
                red_add_v4(op + 4,
                           wt * __uint_as_float(b0), wt * __uint_as_float(b1),
                           wt * __uint_as_float(b2), wt * __uint_as_float(b3));
            }
        }

        pb ^= 1;
        __syncwarp();   // lanes done reading xb/qw before next warp fetch
    }
}

// ---------------- launcher --------------------------------------------------
extern "C" void kernel_launch(void* const* d_in, const int* in_sizes, int n_in,
                              void* d_out, int out_size) {
    const float* q_pts = (const float*)d_in[0];
    const float* s_pts = (const float*)d_in[1];
    const int*   inds  = (const int*)d_in[2];
    const float* x     = (const float*)d_in[3];
    const float* W     = (const float*)d_in[4];
    const float* kpts  = (const float*)d_in[5];
    float*       out   = (float*)d_out;

    int N = in_sizes[0] / 3;
    int M = in_sizes[1] / 3;

    // 0) zero output + counters
    int n4 = out_size / 4;
    zero_kernel<<<(n4 + 255) / 256, 256>>>(out, n4);

    // 1) build per-k entry lists (ballot-compacted)
    int pairs = N * 32;
    build_kernel<<<(pairs + 255) / 256, 256>>>(q_pts, s_pts, inds, x, W, kpts,
                                               out, N, M);

    // 2) warp-decoupled per-k GEMM + scatter
    int smem = (CH * CH + 8 * 2 * WROWS * PAD) * 4
             + 8 * 2 * WROWS * 4 + 8 * 2 * WROWS * 4;   // 88064 B
    cudaFuncSetAttribute(gemm_kernel,
                         cudaFuncAttributeMaxDynamicSharedMemorySize, smem);
    dim3 grid(KK, SLICES);
    gemm_kernel<<<grid, 256, smem>>>(W, x, out);
}